// round 2
// baseline (speedup 1.0000x reference)
#include <cuda_runtime.h>
#include <cstdint>
#include <cstdio>

// ---------------------------------------------------------------------------
// ChessformerAttention: B=512, L=64, H=16, Dh=64, D=1024
//   q,k,v = (x @ W{q,k,v}) -> [B,H,L,Dh]
//   S = q k^T / 8 + bias[h];  P = softmax(S);  O = P v -> [B,L,H*Dh]
//   out = O @ Wo
// Round 1: TF32 mma.sync GEMMs + fp32 fused attention per (b,h).
// ---------------------------------------------------------------------------

#define BM 128
#define BN 128
#define BK 32
#define LDA 36   // BK + 4 pad (conflict-free A fragment loads)
#define LDB 136  // BN + 8 pad (conflict-free B fragment loads)

#define NH 16
#define LSEQ 64
#define DH 64
#define DMODEL 1024

// Scratch (device globals: allocation is forbidden)
__device__ float g_q[512 * 16 * 64 * 64];
__device__ float g_k[512 * 16 * 64 * 64];
__device__ float g_v[512 * 16 * 64 * 64];
__device__ float g_attn[512 * 64 * 1024];

__device__ __forceinline__ uint32_t f2tf32(float f) {
    uint32_t r;
    asm volatile("cvt.rna.tf32.f32 %0, %1;" : "=r"(r) : "f"(f));
    return r;
}

__device__ __forceinline__ void mma_tf32(float* c, const uint32_t* a, const uint32_t* b) {
    asm volatile(
        "mma.sync.aligned.m16n8k8.row.col.f32.tf32.tf32.f32 "
        "{%0,%1,%2,%3}, {%4,%5,%6,%7}, {%8,%9}, {%0,%1,%2,%3};\n"
        : "+f"(c[0]), "+f"(c[1]), "+f"(c[2]), "+f"(c[3])
        : "r"(a[0]), "r"(a[1]), "r"(a[2]), "r"(a[3]),
          "r"(b[0]), "r"(b[1]));
}

// C = A[M,1024] @ W[1024,1024].  permute!=0 -> scatter to [B*H, L, Dh] layout.
__global__ __launch_bounds__(256, 2)
void gemm_tf32(const float* __restrict__ A, const float* __restrict__ W,
               float* __restrict__ out, int permute)
{
    __shared__ uint32_t sA[BM * LDA];
    __shared__ uint32_t sB[BK * LDB];
    const int K = 1024, N = 1024;

    const int t    = threadIdx.x;
    const int lane = t & 31;
    const int warp = t >> 5;
    const int wm   = warp >> 2;   // 0..1
    const int wn   = warp & 3;    // 0..3
    const int bm   = blockIdx.y * BM;
    const int bn   = blockIdx.x * BN;

    float acc[4][4][4];
#pragma unroll
    for (int mi = 0; mi < 4; mi++)
#pragma unroll
        for (int ni = 0; ni < 4; ni++)
#pragma unroll
            for (int e = 0; e < 4; e++) acc[mi][ni][e] = 0.f;

    for (int kt = 0; kt < K; kt += BK) {
        // A tile: 128 rows x 32 cols  (1024 float4, 4 per thread)
#pragma unroll
        for (int i = 0; i < 4; i++) {
            int f  = i * 256 + t;
            int r  = f >> 3;
            int c4 = (f & 7) << 2;
            float4 v = *(const float4*)(A + (size_t)(bm + r) * K + kt + c4);
            uint32_t* d = &sA[r * LDA + c4];
            d[0] = f2tf32(v.x); d[1] = f2tf32(v.y);
            d[2] = f2tf32(v.z); d[3] = f2tf32(v.w);
        }
        // B tile: 32 rows x 128 cols
#pragma unroll
        for (int i = 0; i < 4; i++) {
            int f  = i * 256 + t;
            int r  = f >> 5;
            int c4 = (f & 31) << 2;
            float4 v = *(const float4*)(W + (size_t)(kt + r) * N + bn + c4);
            uint32_t* d = &sB[r * LDB + c4];
            d[0] = f2tf32(v.x); d[1] = f2tf32(v.y);
            d[2] = f2tf32(v.z); d[3] = f2tf32(v.w);
        }
        __syncthreads();

#pragma unroll
        for (int k0 = 0; k0 < BK; k0 += 8) {
            uint32_t a[4][4], b[4][2];
#pragma unroll
            for (int mi = 0; mi < 4; mi++) {
                int row = wm * 64 + mi * 16 + (lane >> 2);
                int kc  = k0 + (lane & 3);
                a[mi][0] = sA[row * LDA + kc];
                a[mi][1] = sA[(row + 8) * LDA + kc];
                a[mi][2] = sA[row * LDA + kc + 4];
                a[mi][3] = sA[(row + 8) * LDA + kc + 4];
            }
#pragma unroll
            for (int ni = 0; ni < 4; ni++) {
                int col = wn * 32 + ni * 8 + (lane >> 2);
                b[ni][0] = sB[(k0 + (lane & 3)) * LDB + col];
                b[ni][1] = sB[(k0 + (lane & 3) + 4) * LDB + col];
            }
#pragma unroll
            for (int mi = 0; mi < 4; mi++)
#pragma unroll
                for (int ni = 0; ni < 4; ni++)
                    mma_tf32(acc[mi][ni], a[mi], b[ni]);
        }
        __syncthreads();
    }

    // Epilogue
#pragma unroll
    for (int mi = 0; mi < 4; mi++) {
#pragma unroll
        for (int ni = 0; ni < 4; ni++) {
#pragma unroll
            for (int e = 0; e < 4; e++) {
                int row = bm + wm * 64 + mi * 16 + (lane >> 2) + ((e >= 2) ? 8 : 0);
                int col = bn + wn * 32 + ni * 8 + ((lane & 3) << 1) + (e & 1);
                float v = acc[mi][ni][e];
                if (permute) {
                    // row = b*64 + l ; col = h*64 + d  ->  [(b*16+h)*64 + l]*64 + d
                    size_t idx = ((size_t)((row >> 6) * 16 + (col >> 6)) << 12)
                               + ((size_t)(row & 63) << 6) + (col & 63);
                    out[idx] = v;
                } else {
                    out[(size_t)row * N + col] = v;
                }
            }
        }
    }
}

// One CTA per (b,h).  256 threads.  Each thread owns a 4x4 strided tile:
// rows i = a*16 + ti (ti = t>>4), cols j = bb*16 + tj (tj = t&15).
__global__ __launch_bounds__(256)
void attn_kernel(const float* __restrict__ Q, const float* __restrict__ K,
                 const float* __restrict__ V, const float* __restrict__ bias,
                 float* __restrict__ out)
{
    __shared__ float sQ[64 * 65];  // reused for P after softmax
    __shared__ float sK[64 * 65];
    __shared__ float sV[64 * 65];

    const int bh = blockIdx.x;       // b*16 + h
    const int h  = bh & 15;
    const int b  = bh >> 4;
    const int t  = threadIdx.x;

    const float* q = Q + (size_t)bh * 4096;
    const float* k = K + (size_t)bh * 4096;
    const float* v = V + (size_t)bh * 4096;

    for (int idx = t; idx < 4096; idx += 256) {
        int i = idx >> 6, d = idx & 63;
        sQ[i * 65 + d] = q[idx];
        sK[i * 65 + d] = k[idx];
        sV[i * 65 + d] = v[idx];
    }
    __syncthreads();

    const int ti = t >> 4;   // 0..15
    const int tj = t & 15;   // 0..15

    // S = Q K^T
    float s[4][4];
#pragma unroll
    for (int a = 0; a < 4; a++)
#pragma unroll
        for (int bb = 0; bb < 4; bb++) s[a][bb] = 0.f;

    for (int d = 0; d < 64; d++) {
        float qv[4], kv[4];
#pragma unroll
        for (int a = 0; a < 4; a++)  qv[a]  = sQ[(a * 16 + ti) * 65 + d];
#pragma unroll
        for (int bb = 0; bb < 4; bb++) kv[bb] = sK[(bb * 16 + tj) * 65 + d];
#pragma unroll
        for (int a = 0; a < 4; a++)
#pragma unroll
            for (int bb = 0; bb < 4; bb++) s[a][bb] += qv[a] * kv[bb];
    }

    // scale + bias + softmax (row groups live in lanes sharing t>>4: 16-lane halves)
    const float* bbias = bias + (size_t)h * 4096;
#pragma unroll
    for (int a = 0; a < 4; a++) {
        int row = a * 16 + ti;
        float m = -1e30f;
#pragma unroll
        for (int bb = 0; bb < 4; bb++) {
            s[a][bb] = s[a][bb] * 0.125f + bbias[row * 64 + bb * 16 + tj];
            m = fmaxf(m, s[a][bb]);
        }
#pragma unroll
        for (int off = 1; off < 16; off <<= 1)
            m = fmaxf(m, __shfl_xor_sync(0xffffffffu, m, off));
        float sum = 0.f;
#pragma unroll
        for (int bb = 0; bb < 4; bb++) {
            float p = __expf(s[a][bb] - m);
            s[a][bb] = p;
            sum += p;
        }
#pragma unroll
        for (int off = 1; off < 16; off <<= 1)
            sum += __shfl_xor_sync(0xffffffffu, sum, off);
        float inv = 1.f / sum;
#pragma unroll
        for (int bb = 0; bb < 4; bb++) s[a][bb] *= inv;
    }

    __syncthreads();  // everyone done reading sQ
#pragma unroll
    for (int a = 0; a < 4; a++)
#pragma unroll
        for (int bb = 0; bb < 4; bb++)
            sQ[(a * 16 + ti) * 65 + bb * 16 + tj] = s[a][bb];  // sQ := P
    __syncthreads();

    // O = P V  (thread owns rows i = a*16+ti, out-cols d = bb*16+tj)
    float o[4][4];
#pragma unroll
    for (int a = 0; a < 4; a++)
#pragma unroll
        for (int bb = 0; bb < 4; bb++) o[a][bb] = 0.f;

    for (int j = 0; j < 64; j++) {
        float pv[4], vv[4];
#pragma unroll
        for (int a = 0; a < 4; a++)  pv[a]  = sQ[(a * 16 + ti) * 65 + j];
#pragma unroll
        for (int bb = 0; bb < 4; bb++) vv[bb] = sV[j * 65 + bb * 16 + tj];
#pragma unroll
        for (int a = 0; a < 4; a++)
#pragma unroll
            for (int bb = 0; bb < 4; bb++) o[a][bb] += pv[a] * vv[bb];
    }

    // out[b][l][h*64 + d]  (row-major [B*L, 1024])
#pragma unroll
    for (int a = 0; a < 4; a++) {
        int i = a * 16 + ti;
#pragma unroll
        for (int bb = 0; bb < 4; bb++) {
            int d = bb * 16 + tj;
            out[((size_t)(b * 64 + i)) * 1024 + h * 64 + d] = o[a][bb];
        }
    }
}

extern "C" void kernel_launch(void* const* d_in, const int* in_sizes, int n_in,
                              void* d_out, int out_size)
{
    const float* x    = (const float*)d_in[0];
    const float* bias = (const float*)d_in[1];
    const float* Wq   = (const float*)d_in[2];
    const float* Wk   = (const float*)d_in[3];
    const float* Wv   = (const float*)d_in[4];
    const float* Wo   = (const float*)d_in[5];
    float* out = (float*)d_out;

    float *gq, *gk, *gv, *ga;
    cudaGetSymbolAddress((void**)&gq, g_q);
    cudaGetSymbolAddress((void**)&gk, g_k);
    cudaGetSymbolAddress((void**)&gv, g_v);
    cudaGetSymbolAddress((void**)&ga, g_attn);

    dim3 ggrid(DMODEL / BN, (512 * 64) / BM);  // (8, 256)
    gemm_tf32<<<ggrid, 256>>>(x, Wq, gq, 1);
    gemm_tf32<<<ggrid, 256>>>(x, Wk, gk, 1);
    gemm_tf32<<<ggrid, 256>>>(x, Wv, gv, 1);

    attn_kernel<<<512 * 16, 256>>>(gq, gk, gv, bias, ga);

    gemm_tf32<<<ggrid, 256>>>(ga, Wo, out, 0);
}

// round 3
// speedup vs baseline: 1.0136x; 1.0136x over previous
#include <cuda_runtime.h>
#include <cstdint>

// ---------------------------------------------------------------------------
// ChessformerAttention: B=512, L=64, H=16, Dh=64, D=1024
// Round 2: cp.async double-buffered TF32 GEMMs + pre-rounded (cvt.rna) inputs.
//   q,k,v = (x @ W{q,k,v}) -> [B,H,L,Dh]
//   S = q k^T / 8 + bias[h];  P = softmax(S);  O = P v -> [B,L,H*Dh]
//   out = O @ Wo
// ---------------------------------------------------------------------------

#define BM 128
#define BN 128
#define GBK 16
#define LDA 20    // 16 + 4 pad (80B rows, 16B aligned, conflict-free frags)
#define LDB 136   // 128 + 8 pad (544B rows, 16B aligned, conflict-free frags)

// Scratch (device globals: allocation is forbidden)
__device__ float g_x [512 * 64 * 1024];
__device__ float g_wq[1024 * 1024];
__device__ float g_wk[1024 * 1024];
__device__ float g_wv[1024 * 1024];
__device__ float g_wo[1024 * 1024];
__device__ float g_q [512 * 16 * 64 * 64];
__device__ float g_k [512 * 16 * 64 * 64];
__device__ float g_v [512 * 16 * 64 * 64];
__device__ float g_attn[512 * 64 * 1024];

__device__ __forceinline__ float tf32f(float f) {
    uint32_t r;
    asm volatile("cvt.rna.tf32.f32 %0, %1;" : "=r"(r) : "f"(f));
    return __uint_as_float(r);
}

__device__ __forceinline__ void mma_tf32(float* c, const uint32_t* a, const uint32_t* b) {
    asm volatile(
        "mma.sync.aligned.m16n8k8.row.col.f32.tf32.tf32.f32 "
        "{%0,%1,%2,%3}, {%4,%5,%6,%7}, {%8,%9}, {%0,%1,%2,%3};\n"
        : "+f"(c[0]), "+f"(c[1]), "+f"(c[2]), "+f"(c[3])
        : "r"(a[0]), "r"(a[1]), "r"(a[2]), "r"(a[3]),
          "r"(b[0]), "r"(b[1]));
}

__device__ __forceinline__ void cpa16(void* s, const void* g) {
    uint32_t sa = (uint32_t)__cvta_generic_to_shared(s);
    asm volatile("cp.async.cg.shared.global [%0], [%1], 16;\n" :: "r"(sa), "l"(g));
}
__device__ __forceinline__ void cpa_commit() {
    asm volatile("cp.async.commit_group;\n" ::: "memory");
}
__device__ __forceinline__ void cpa_wait_all() {
    asm volatile("cp.async.wait_group 0;\n" ::: "memory");
}

// Pre-round tensors to TF32 (RNA) so the GEMM can use raw cp.async copies.
__global__ void round4_kernel(const float* __restrict__ in, float* __restrict__ out, int n4) {
    int i = blockIdx.x * blockDim.x + threadIdx.x;
    int stride = gridDim.x * blockDim.x;
    for (; i < n4; i += stride) {
        float4 v = ((const float4*)in)[i];
        v.x = tf32f(v.x); v.y = tf32f(v.y); v.z = tf32f(v.z); v.w = tf32f(v.w);
        ((float4*)out)[i] = v;
    }
}

// C = A[M,1024] @ W[1024,1024].  Inputs MUST already be tf32-rounded.
// permute!=0 -> scatter to [B*H, L, Dh] layout.
__global__ __launch_bounds__(256, 2)
void gemm_tf32(const float* __restrict__ A, const float* __restrict__ W,
               float* __restrict__ out, int permute)
{
    __shared__ float sA[2][BM * LDA];   // 20480 B
    __shared__ float sB[2][GBK * LDB];  // 17408 B
    const int K = 1024, N = 1024;

    const int t    = threadIdx.x;
    const int lane = t & 31;
    const int warp = t >> 5;
    const int wm   = warp >> 2;   // 0..1
    const int wn   = warp & 3;    // 0..3
    const int bm   = blockIdx.y * BM;
    const int bn   = blockIdx.x * BN;

    // cp.async chunk assignment (16B chunks)
    // A tile: 128 rows x 16 floats = 512 chunks; thread does chunks t and t+256
    const int ar0 = t >> 2;               // 0..63
    const int ar1 = ar0 + 64;             // 64..127
    const int ac  = (t & 3) << 2;         // 0,4,8,12
    // B tile: 16 rows x 128 floats = 512 chunks
    const int br0 = t >> 5;               // 0..7
    const int br1 = br0 + 8;              // 8..15
    const int bc  = (t & 31) << 2;        // 0..124

    const float* A0 = A + (size_t)(bm + ar0) * K + ac;
    const float* A1 = A + (size_t)(bm + ar1) * K + ac;
    const float* W0 = W + (size_t)br0 * N + bn + bc;
    const float* W1 = W + (size_t)br1 * N + bn + bc;

    float acc[4][4][4];
#pragma unroll
    for (int mi = 0; mi < 4; mi++)
#pragma unroll
        for (int ni = 0; ni < 4; ni++)
#pragma unroll
            for (int e = 0; e < 4; e++) acc[mi][ni][e] = 0.f;

    // prologue: issue tile 0
    {
        cpa16(&sA[0][ar0 * LDA + ac], A0);
        cpa16(&sA[0][ar1 * LDA + ac], A1);
        cpa16(&sB[0][br0 * LDB + bc], W0);
        cpa16(&sB[0][br1 * LDB + bc], W1);
        cpa_commit();
    }

    const int NIT = K / GBK;  // 64
    for (int it = 0; it < NIT; it++) {
        const int s = it & 1;
        cpa_wait_all();
        __syncthreads();

        if (it < NIT - 1) {
            const int kt = (it + 1) * GBK;
            cpa16(&sA[s ^ 1][ar0 * LDA + ac], A0 + kt);
            cpa16(&sA[s ^ 1][ar1 * LDA + ac], A1 + kt);
            cpa16(&sB[s ^ 1][br0 * LDB + bc], W0 + (size_t)kt * N);
            cpa16(&sB[s ^ 1][br1 * LDB + bc], W1 + (size_t)kt * N);
            cpa_commit();
        }

        const uint32_t* cA = (const uint32_t*)sA[s];
        const uint32_t* cB = (const uint32_t*)sB[s];
#pragma unroll
        for (int k0 = 0; k0 < GBK; k0 += 8) {
            uint32_t a[4][4], b[4][2];
            const int kc = k0 + (lane & 3);
#pragma unroll
            for (int mi = 0; mi < 4; mi++) {
                int row = wm * 64 + mi * 16 + (lane >> 2);
                a[mi][0] = cA[row * LDA + kc];
                a[mi][1] = cA[(row + 8) * LDA + kc];
                a[mi][2] = cA[row * LDA + kc + 4];
                a[mi][3] = cA[(row + 8) * LDA + kc + 4];
            }
#pragma unroll
            for (int ni = 0; ni < 4; ni++) {
                int col = wn * 32 + ni * 8 + (lane >> 2);
                b[ni][0] = cB[kc * LDB + col];
                b[ni][1] = cB[(kc + 4) * LDB + col];
            }
#pragma unroll
            for (int mi = 0; mi < 4; mi++)
#pragma unroll
                for (int ni = 0; ni < 4; ni++)
                    mma_tf32(acc[mi][ni], a[mi], b[ni]);
        }
        __syncthreads();
    }

    // Epilogue
#pragma unroll
    for (int mi = 0; mi < 4; mi++) {
#pragma unroll
        for (int ni = 0; ni < 4; ni++) {
#pragma unroll
            for (int e = 0; e < 4; e++) {
                int row = bm + wm * 64 + mi * 16 + (lane >> 2) + ((e >= 2) ? 8 : 0);
                int col = bn + wn * 32 + ni * 8 + ((lane & 3) << 1) + (e & 1);
                float v = acc[mi][ni][e];
                if (permute) {
                    // row = b*64 + l ; col = h*64 + d  ->  [(b*16+h)*64 + l]*64 + d
                    size_t idx = ((size_t)((row >> 6) * 16 + (col >> 6)) << 12)
                               + ((size_t)(row & 63) << 6) + (col & 63);
                    out[idx] = v;
                } else {
                    out[(size_t)row * N + col] = v;
                }
            }
        }
    }
}

// One CTA per (b,h).  256 threads.  Each thread owns a 4x4 strided tile.
// Output is stored tf32-rounded (feeds the final cp.async GEMM).
__global__ __launch_bounds__(256)
void attn_kernel(const float* __restrict__ Q, const float* __restrict__ K,
                 const float* __restrict__ V, const float* __restrict__ bias,
                 float* __restrict__ out)
{
    __shared__ float sQ[64 * 65];  // reused for P after softmax
    __shared__ float sK[64 * 65];
    __shared__ float sV[64 * 65];

    const int bh = blockIdx.x;       // b*16 + h
    const int h  = bh & 15;
    const int b  = bh >> 4;
    const int t  = threadIdx.x;

    const float* q = Q + (size_t)bh * 4096;
    const float* k = K + (size_t)bh * 4096;
    const float* v = V + (size_t)bh * 4096;

    for (int idx = t; idx < 4096; idx += 256) {
        int i = idx >> 6, d = idx & 63;
        sQ[i * 65 + d] = q[idx];
        sK[i * 65 + d] = k[idx];
        sV[i * 65 + d] = v[idx];
    }
    __syncthreads();

    const int ti = t >> 4;   // 0..15
    const int tj = t & 15;   // 0..15

    // S = Q K^T
    float s[4][4];
#pragma unroll
    for (int a = 0; a < 4; a++)
#pragma unroll
        for (int bb = 0; bb < 4; bb++) s[a][bb] = 0.f;

    for (int d = 0; d < 64; d++) {
        float qv[4], kv[4];
#pragma unroll
        for (int a = 0; a < 4; a++)  qv[a]  = sQ[(a * 16 + ti) * 65 + d];
#pragma unroll
        for (int bb = 0; bb < 4; bb++) kv[bb] = sK[(bb * 16 + tj) * 65 + d];
#pragma unroll
        for (int a = 0; a < 4; a++)
#pragma unroll
            for (int bb = 0; bb < 4; bb++) s[a][bb] += qv[a] * kv[bb];
    }

    // scale + bias + softmax (16-lane groups share a row)
    const float* bbias = bias + (size_t)h * 4096;
#pragma unroll
    for (int a = 0; a < 4; a++) {
        int row = a * 16 + ti;
        float m = -1e30f;
#pragma unroll
        for (int bb = 0; bb < 4; bb++) {
            s[a][bb] = s[a][bb] * 0.125f + bbias[row * 64 + bb * 16 + tj];
            m = fmaxf(m, s[a][bb]);
        }
#pragma unroll
        for (int off = 1; off < 16; off <<= 1)
            m = fmaxf(m, __shfl_xor_sync(0xffffffffu, m, off));
        float sum = 0.f;
#pragma unroll
        for (int bb = 0; bb < 4; bb++) {
            float p = __expf(s[a][bb] - m);
            s[a][bb] = p;
            sum += p;
        }
#pragma unroll
        for (int off = 1; off < 16; off <<= 1)
            sum += __shfl_xor_sync(0xffffffffu, sum, off);
        float inv = 1.f / sum;
#pragma unroll
        for (int bb = 0; bb < 4; bb++) s[a][bb] *= inv;
    }

    __syncthreads();  // everyone done reading sQ
#pragma unroll
    for (int a = 0; a < 4; a++)
#pragma unroll
        for (int bb = 0; bb < 4; bb++)
            sQ[(a * 16 + ti) * 65 + bb * 16 + tj] = s[a][bb];  // sQ := P
    __syncthreads();

    // O = P V
    float o[4][4];
#pragma unroll
    for (int a = 0; a < 4; a++)
#pragma unroll
        for (int bb = 0; bb < 4; bb++) o[a][bb] = 0.f;

    for (int j = 0; j < 64; j++) {
        float pv[4], vv[4];
#pragma unroll
        for (int a = 0; a < 4; a++)  pv[a]  = sQ[(a * 16 + ti) * 65 + j];
#pragma unroll
        for (int bb = 0; bb < 4; bb++) vv[bb] = sV[j * 65 + bb * 16 + tj];
#pragma unroll
        for (int a = 0; a < 4; a++)
#pragma unroll
            for (int bb = 0; bb < 4; bb++) o[a][bb] += pv[a] * vv[bb];
    }

    // out[b][l][h*64 + d]  (row-major [B*L, 1024]), tf32-rounded for next GEMM
#pragma unroll
    for (int a = 0; a < 4; a++) {
        int i = a * 16 + ti;
#pragma unroll
        for (int bb = 0; bb < 4; bb++) {
            int d = bb * 16 + tj;
            out[((size_t)(b * 64 + i)) * 1024 + h * 64 + d] = tf32f(o[a][bb]);
        }
    }
}

extern "C" void kernel_launch(void* const* d_in, const int* in_sizes, int n_in,
                              void* d_out, int out_size)
{
    const float* x    = (const float*)d_in[0];
    const float* bias = (const float*)d_in[1];
    const float* Wq   = (const float*)d_in[2];
    const float* Wk   = (const float*)d_in[3];
    const float* Wv   = (const float*)d_in[4];
    const float* Wo   = (const float*)d_in[5];
    float* out = (float*)d_out;

    float *gx, *gwq, *gwk, *gwv, *gwo, *gq, *gk, *gv, *ga;
    cudaGetSymbolAddress((void**)&gx,  g_x);
    cudaGetSymbolAddress((void**)&gwq, g_wq);
    cudaGetSymbolAddress((void**)&gwk, g_wk);
    cudaGetSymbolAddress((void**)&gwv, g_wv);
    cudaGetSymbolAddress((void**)&gwo, g_wo);
    cudaGetSymbolAddress((void**)&gq,  g_q);
    cudaGetSymbolAddress((void**)&gk,  g_k);
    cudaGetSymbolAddress((void**)&gv,  g_v);
    cudaGetSymbolAddress((void**)&ga,  g_attn);

    // Pre-round to tf32 (RNA)
    round4_kernel<<<2048, 256>>>(x,  gx,  (512 * 64 * 1024) / 4);
    round4_kernel<<<256,  256>>>(Wq, gwq, (1024 * 1024) / 4);
    round4_kernel<<<256,  256>>>(Wk, gwk, (1024 * 1024) / 4);
    round4_kernel<<<256,  256>>>(Wv, gwv, (1024 * 1024) / 4);
    round4_kernel<<<256,  256>>>(Wo, gwo, (1024 * 1024) / 4);

    dim3 ggrid(1024 / BN, (512 * 64) / BM);  // (8, 256)
    gemm_tf32<<<ggrid, 256>>>(gx, gwq, gq, 1);
    gemm_tf32<<<ggrid, 256>>>(gx, gwk, gk, 1);
    gemm_tf32<<<ggrid, 256>>>(gx, gwv, gv, 1);

    attn_kernel<<<512 * 16, 256>>>(gq, gk, gv, bias, ga);

    gemm_tf32<<<ggrid, 256>>>(ga, gwo, out, 0);
}